// round 1
// baseline (speedup 1.0000x reference)
#include <cuda_runtime.h>
#include <cuda_bf16.h>
#include <cstdint>

#define SEQ   65536
#define HID   1024
#define EMB   512
#define NCH   512
#define GCTA  128        // scan CTAs
#define RROW  8          // rows of Waa per CTA (1024/128)

// ---------------- device scratch (static allocation only) ----------------
struct __align__(8) Pub { unsigned int v; unsigned int tag; };
__device__ Pub   g_h[2][HID];                    // ping-pong (value,tag) pairs
__device__ float g_xp[(size_t)SEQ * HID];        // x projections  (256 MB)
__device__ float g_hs[(size_t)SEQ * HID];        // hidden states  (256 MB)

// ---------------- small helpers ----------------
__device__ __forceinline__ void st_pair(Pub* p, float val, unsigned tag) {
    unsigned long long u = ((unsigned long long)tag << 32) |
                           (unsigned long long)__float_as_uint(val);
    asm volatile("st.global.relaxed.gpu.b64 [%0], %1;" :: "l"(p), "l"(u) : "memory");
}
__device__ __forceinline__ unsigned long long ld_pair(const Pub* p) {
    unsigned long long u;
    asm volatile("ld.global.relaxed.gpu.b64 %0, [%1];" : "=l"(u) : "l"(p) : "memory");
    return u;
}

// ---------------- init: clear tags each launch (graph replays!) ----------------
__global__ void init_tags_kernel() {
    unsigned long long* p = (unsigned long long*)g_h;
    for (int i = threadIdx.x; i < 2 * HID; i += blockDim.x) p[i] = 0ULL;
}

// ---------------- fp32 SGEMM:  C[M,N] = A[M,K] * B[N,K]^T (+bias) ----------------
// A optionally row-gathered through idx (embedding lookup).
// 128x128 tile, BK=8, 256 threads, 8x8 microtile.
template<bool GATHER, bool BIAS>
__global__ void __launch_bounds__(256) sgemm_tn(
    const float* __restrict__ A, const float* __restrict__ B,
    float* __restrict__ C, const int* __restrict__ idx,
    const float* __restrict__ bias, int M, int N, int K)
{
    __shared__ __align__(16) float As[8][132];
    __shared__ __align__(16) float Bs[8][132];
    __shared__ int sidx[128];

    const int tid = threadIdx.x;
    const int bm  = blockIdx.y * 128;
    const int bn  = blockIdx.x * 128;

    if (GATHER && tid < 128) sidx[tid] = idx[bm + tid];
    __syncthreads();

    const int tx = tid & 15;          // 0..15 -> n
    const int ty = tid >> 4;          // 0..15 -> m
    const int arow = tid >> 1;        // 0..127
    const int akq  = (tid & 1) * 4;   // 0 or 4

    const float* Arow = GATHER ? (A + (size_t)sidx[arow] * K)
                               : (A + (size_t)(bm + arow) * K);
    const float* Brow = B + (size_t)(bn + arow) * K;

    float acc[8][8];
    #pragma unroll
    for (int i = 0; i < 8; i++)
        #pragma unroll
        for (int j = 0; j < 8; j++) acc[i][j] = 0.f;

    for (int kt = 0; kt < K; kt += 8) {
        float4 av = *(const float4*)(Arow + kt + akq);
        float4 bv = *(const float4*)(Brow + kt + akq);
        __syncthreads();
        As[akq+0][arow] = av.x; As[akq+1][arow] = av.y;
        As[akq+2][arow] = av.z; As[akq+3][arow] = av.w;
        Bs[akq+0][arow] = bv.x; Bs[akq+1][arow] = bv.y;
        Bs[akq+2][arow] = bv.z; Bs[akq+3][arow] = bv.w;
        __syncthreads();
        #pragma unroll
        for (int k = 0; k < 8; k++) {
            float ra[8], rb[8];
            #pragma unroll
            for (int i = 0; i < 8; i++) ra[i] = As[k][ty * 8 + i];
            #pragma unroll
            for (int j = 0; j < 8; j++) rb[j] = Bs[k][tx * 8 + j];
            #pragma unroll
            for (int i = 0; i < 8; i++)
                #pragma unroll
                for (int j = 0; j < 8; j++) acc[i][j] += ra[i] * rb[j];
        }
    }

    float bload[8];
    #pragma unroll
    for (int j = 0; j < 8; j++) bload[j] = BIAS ? bias[bn + tx * 8 + j] : 0.f;

    #pragma unroll
    for (int i = 0; i < 8; i++) {
        size_t row = (size_t)(bm + ty * 8 + i);
        float* cp = C + row * N + bn + tx * 8;
        float4 v0, v1;
        v0.x = acc[i][0] + bload[0]; v0.y = acc[i][1] + bload[1];
        v0.z = acc[i][2] + bload[2]; v0.w = acc[i][3] + bload[3];
        v1.x = acc[i][4] + bload[4]; v1.y = acc[i][5] + bload[5];
        v1.z = acc[i][6] + bload[6]; v1.w = acc[i][7] + bload[7];
        *(float4*)(cp)     = v0;
        *(float4*)(cp + 4) = v1;
    }
}

// ---------------- the scan: 128 persistent CTAs, tag-published h ----------------
__global__ void __launch_bounds__(256, 1) scan_kernel(const float* __restrict__ Waa)
{
    __shared__ __align__(16) float sWaa[RROW][HID];   // 32 KB, this CTA's rows (fp32!)
    __shared__ __align__(16) float sh[HID];           // staged h_t
    __shared__ float sred[8][RROW];

    const int tid  = threadIdx.x;
    const int cta  = blockIdx.x;
    const int row0 = cta * RROW;
    const int w = tid >> 5, l = tid & 31;

    // load Waa slice into SMEM (fp32 for exact precision)
    {
        const float4* src = (const float4*)(Waa + (size_t)row0 * HID);
        float4* dst = (float4*)&sWaa[0][0];
        #pragma unroll
        for (int i = tid; i < RROW * HID / 4; i += 256) dst[i] = src[i];
    }

    // step 0: h_1 = tanh(xp[0])  (h_0 == 0, no matvec, no wait)
    if (tid < RROW) {
        float v = tanhf(g_xp[row0 + tid]);
        g_hs[row0 + tid] = v;
        st_pair(&g_h[1][row0 + tid], v, 1u);
    }
    __syncthreads();  // Waa tile ready

    for (int s = 1; s < SEQ; s++) {
        // prefetch this step's xp (independent of h -> overlaps the polling)
        float xpv = 0.f;
        if (tid < RROW) xpv = __ldcg(&g_xp[(size_t)s * HID + row0 + tid]);

        const int slot = s & 1;
        // stage h_s: each thread owns 4 (value,tag) pairs
        #pragma unroll
        for (int j = 0; j < 4; j++) {
            const int gi = tid * 4 + j;
            unsigned long long u = ld_pair(&g_h[slot][gi]);
            while ((unsigned)(u >> 32) != (unsigned)s) {
                __nanosleep(20);
                u = ld_pair(&g_h[slot][gi]);
            }
            sh[gi] = __uint_as_float((unsigned)u);
        }
        __syncthreads();

        // warp w covers cols [w*128, w*128+128); lane l covers 4 cols
        const int c0 = w * 128 + l * 4;
        const float4 hv = *(const float4*)&sh[c0];
        float acc[RROW];
        #pragma unroll
        for (int r = 0; r < RROW; r++) {
            const float4 wv = *(const float4*)&sWaa[r][c0];
            acc[r] = wv.x * hv.x + wv.y * hv.y + wv.z * hv.z + wv.w * hv.w;
        }
        // butterfly reduce within warp
        #pragma unroll
        for (int off = 16; off > 0; off >>= 1)
            #pragma unroll
            for (int r = 0; r < RROW; r++)
                acc[r] += __shfl_xor_sync(0xffffffffu, acc[r], off);
        if (l == 0)
            #pragma unroll
            for (int r = 0; r < RROW; r++) sred[w][r] = acc[r];
        __syncthreads();

        // finalize 8 rows, publish h_{s+1}
        if (tid < RROW) {
            float sum = xpv;
            #pragma unroll
            for (int ww = 0; ww < 8; ww++) sum += sred[ww][tid];
            const float v = tanhf(sum);
            g_hs[(size_t)s * HID + row0 + tid] = v;
            st_pair(&g_h[(s + 1) & 1][row0 + tid], v, (unsigned)(s + 1));
        }
        // no trailing barrier needed: next staging only touches sh (dead after
        // sync #2) and is gated by tags; sred of step s+1 is written only after
        // sync #1 of s+1, which warp 0 reaches after its sred reads.
    }
}

// ---------------- h_last epilogue ----------------
__global__ void copy_hlast_kernel(float* __restrict__ out) {
    const int i = threadIdx.x;                 // 1024 threads
    out[(size_t)SEQ * NCH + i] = __uint_as_float(g_h[0][i].v);  // h_S lives in slot 0 (S even)
}

// ---------------- launch ----------------
extern "C" void kernel_launch(void* const* d_in, const int* in_sizes, int n_in,
                              void* d_out, int out_size)
{
    const int*   input_seq = (const int*)  d_in[0];
    const float* emb       = (const float*)d_in[1];
    const float* Wax       = (const float*)d_in[2];
    const float* Waa       = (const float*)d_in[3];
    const float* Wya       = (const float*)d_in[4];
    const float* b_y       = (const float*)d_in[5];
    float* out = (float*)d_out;

    float* xp_ptr = nullptr;
    float* hs_ptr = nullptr;
    cudaGetSymbolAddress((void**)&xp_ptr, g_xp);
    cudaGetSymbolAddress((void**)&hs_ptr, g_hs);

    // 1) x_proj[s,h] = sum_e emb_table[input_seq[s],e] * Wax[h,e]
    {
        dim3 grid(HID / 128, SEQ / 128);
        sgemm_tn<true, false><<<grid, 256>>>(emb, Wax, xp_ptr, input_seq, nullptr,
                                             SEQ, HID, EMB);
    }
    // 2) reset publish tags, then the sequential scan
    init_tags_kernel<<<1, 256>>>();
    scan_kernel<<<GCTA, 256>>>(Waa);
    // 3) out[s,v] = sum_h hs[s,h] * Wya[v,h] + b_y[v]
    {
        dim3 grid(NCH / 128, SEQ / 128);
        sgemm_tn<false, true><<<grid, 256>>>(hs_ptr, Wya, out, nullptr, b_y,
                                             SEQ, NCH, HID);
    }
    // 4) append h_last
    copy_hlast_kernel<<<1, HID>>>(out);
}

// round 2
// speedup vs baseline: 1.9150x; 1.9150x over previous
#include <cuda_runtime.h>
#include <cuda_bf16.h>
#include <cstdint>

#define SEQ   65536
#define HID   1024
#define EMB   512
#define NCH   512
#define GCTA  128        // scan CTAs
#define RROW  8          // rows of Waa per CTA (1024/128)

// ---------------- device scratch (static allocation only) ----------------
struct __align__(8) Pub { unsigned int v; unsigned int tag; };
__device__ Pub   g_h[2][HID];                    // ping-pong (value,tag) pairs
__device__ float g_xp[(size_t)SEQ * HID];        // x projections  (256 MB)
__device__ float g_hs[(size_t)SEQ * HID];        // hidden states  (256 MB)

// ---------------- small helpers ----------------
__device__ __forceinline__ void st_pair(Pub* p, float val, unsigned tag) {
    unsigned long long u = ((unsigned long long)tag << 32) |
                           (unsigned long long)__float_as_uint(val);
    asm volatile("st.global.relaxed.gpu.b64 [%0], %1;" :: "l"(p), "l"(u) : "memory");
}
__device__ __forceinline__ unsigned long long ld_pair(const Pub* p) {
    unsigned long long u;
    asm volatile("ld.global.relaxed.gpu.b64 %0, [%1];" : "=l"(u) : "l"(p) : "memory");
    return u;
}

// ---------------- init: clear tags each launch (graph replays!) ----------------
__global__ void init_tags_kernel() {
    unsigned long long* p = (unsigned long long*)g_h;
    for (int i = threadIdx.x; i < 2 * HID; i += blockDim.x) p[i] = 0ULL;
}

// ---------------- fp32 SGEMM:  C[M,N] = A[M,K] * B[N,K]^T (+bias) ----------------
template<bool GATHER, bool BIAS>
__global__ void __launch_bounds__(256) sgemm_tn(
    const float* __restrict__ A, const float* __restrict__ B,
    float* __restrict__ C, const int* __restrict__ idx,
    const float* __restrict__ bias, int M, int N, int K)
{
    __shared__ __align__(16) float As[8][132];
    __shared__ __align__(16) float Bs[8][132];
    __shared__ int sidx[128];

    const int tid = threadIdx.x;
    const int bm  = blockIdx.y * 128;
    const int bn  = blockIdx.x * 128;

    if (GATHER && tid < 128) sidx[tid] = idx[bm + tid];
    __syncthreads();

    const int tx = tid & 15;          // 0..15 -> n
    const int ty = tid >> 4;          // 0..15 -> m
    const int arow = tid >> 1;        // 0..127
    const int akq  = (tid & 1) * 4;   // 0 or 4

    const float* Arow = GATHER ? (A + (size_t)sidx[arow] * K)
                               : (A + (size_t)(bm + arow) * K);
    const float* Brow = B + (size_t)(bn + arow) * K;

    float acc[8][8];
    #pragma unroll
    for (int i = 0; i < 8; i++)
        #pragma unroll
        for (int j = 0; j < 8; j++) acc[i][j] = 0.f;

    for (int kt = 0; kt < K; kt += 8) {
        float4 av = *(const float4*)(Arow + kt + akq);
        float4 bv = *(const float4*)(Brow + kt + akq);
        __syncthreads();
        As[akq+0][arow] = av.x; As[akq+1][arow] = av.y;
        As[akq+2][arow] = av.z; As[akq+3][arow] = av.w;
        Bs[akq+0][arow] = bv.x; Bs[akq+1][arow] = bv.y;
        Bs[akq+2][arow] = bv.z; Bs[akq+3][arow] = bv.w;
        __syncthreads();
        #pragma unroll
        for (int k = 0; k < 8; k++) {
            float ra[8], rb[8];
            #pragma unroll
            for (int i = 0; i < 8; i++) ra[i] = As[k][ty * 8 + i];
            #pragma unroll
            for (int j = 0; j < 8; j++) rb[j] = Bs[k][tx * 8 + j];
            #pragma unroll
            for (int i = 0; i < 8; i++)
                #pragma unroll
                for (int j = 0; j < 8; j++) acc[i][j] += ra[i] * rb[j];
        }
    }

    float bload[8];
    #pragma unroll
    for (int j = 0; j < 8; j++) bload[j] = BIAS ? bias[bn + tx * 8 + j] : 0.f;

    #pragma unroll
    for (int i = 0; i < 8; i++) {
        size_t row = (size_t)(bm + ty * 8 + i);
        float* cp = C + row * N + bn + tx * 8;
        float4 v0, v1;
        v0.x = acc[i][0] + bload[0]; v0.y = acc[i][1] + bload[1];
        v0.z = acc[i][2] + bload[2]; v0.w = acc[i][3] + bload[3];
        v1.x = acc[i][4] + bload[4]; v1.y = acc[i][5] + bload[5];
        v1.z = acc[i][6] + bload[6]; v1.w = acc[i][7] + bload[7];
        *(float4*)(cp)     = v0;
        *(float4*)(cp + 4) = v1;
    }
}

// ---------------- the scan ----------------
// 128 CTAs x 1024 threads. Every thread polls exactly ONE (val,tag) pair.
// Warps 0..15 are compute warps: each thread holds a 2-row x 8-col patch of
// Waa in REGISTERS (no per-step weight streaming from SMEM).
//   warp w (w<16): row pair p = w>>2 (local rows 2p,2p+1), quarter q = w&3,
//   lane l: column strip = q*32+l, cols [strip*8, strip*8+8).
__global__ void __launch_bounds__(1024, 1) scan_kernel(const float* __restrict__ Waa)
{
    __shared__ __align__(16) float sh[HID];     // staged h_t
    __shared__ float sred[RROW][4];             // per-quarter partials

    const int tid  = threadIdx.x;
    const int cta  = blockIdx.x;
    const int row0 = cta * RROW;
    const int w = tid >> 5, l = tid & 31;
    const bool is_compute = (w < 16);

    // load this thread's weight patch into registers
    float4 w0a, w0b, w1a, w1b;
    int strip = 0, rloc = 0;
    if (is_compute) {
        const int p = w >> 2;
        const int q = w & 3;
        strip = q * 32 + l;
        rloc  = 2 * p;
        const float* base = Waa + (size_t)(row0 + rloc) * HID + strip * 8;
        w0a = *(const float4*)(base);
        w0b = *(const float4*)(base + 4);
        w1a = *(const float4*)(base + HID);
        w1b = *(const float4*)(base + HID + 4);
    }

    // step 0: h_1 = tanh(xp[0])  (h_0 == 0 -> no matvec, no wait)
    if (tid < RROW) {
        float v = tanhf(g_xp[row0 + tid]);
        g_hs[row0 + tid] = v;
        st_pair(&g_h[1][row0 + tid], v, 1u);
    }

    for (int s = 1; s < SEQ; s++) {
        // prefetch this step's xp (independent of h -> overlaps the polling)
        float xpv = 0.f;
        if (tid < RROW) xpv = __ldcg(&g_xp[(size_t)s * HID + row0 + tid]);

        // stage h_s: one pair per thread, single L2 round trip to detect
        {
            const Pub* p = &g_h[s & 1][tid];
            unsigned long long u = ld_pair(p);
            while ((unsigned)(u >> 32) != (unsigned)s) {
                __nanosleep(10);
                u = ld_pair(p);
            }
            sh[tid] = __uint_as_float((unsigned)u);
        }
        __syncthreads();   // bar0: sh fully staged

        if (is_compute) {
            const float4 h0 = *(const float4*)&sh[strip * 8];
            const float4 h1 = *(const float4*)&sh[strip * 8 + 4];
            float a0 = w0a.x*h0.x + w0a.y*h0.y + w0a.z*h0.z + w0a.w*h0.w
                     + w0b.x*h1.x + w0b.y*h1.y + w0b.z*h1.z + w0b.w*h1.w;
            float a1 = w1a.x*h0.x + w1a.y*h0.y + w1a.z*h0.z + w1a.w*h0.w
                     + w1b.x*h1.x + w1b.y*h1.y + w1b.z*h1.z + w1b.w*h1.w;
            #pragma unroll
            for (int off = 16; off > 0; off >>= 1) {
                a0 += __shfl_xor_sync(0xffffffffu, a0, off);
                a1 += __shfl_xor_sync(0xffffffffu, a1, off);
            }
            if (l == 0) {
                sred[rloc    ][w & 3] = a0;
                sred[rloc + 1][w & 3] = a1;
            }
        }
        __syncthreads();   // bar1: sred ready; also protects sh from next-step staging

        // finalize 8 rows, publish h_{s+1}
        if (tid < RROW) {
            const float sum = xpv + sred[tid][0] + sred[tid][1]
                                  + sred[tid][2] + sred[tid][3];
            const float v = tanhf(sum);
            g_hs[(size_t)s * HID + row0 + tid] = v;
            st_pair(&g_h[(s + 1) & 1][row0 + tid], v, (unsigned)(s + 1));
        }
        // no trailing barrier: next staging writes sh[tid] only after bar1,
        // and all sh reads of step s precede bar1; sred(s+1) writes happen
        // after bar0(s+1), which the finalize threads must also reach.
    }
}

// ---------------- h_last epilogue ----------------
__global__ void copy_hlast_kernel(float* __restrict__ out) {
    const int i = threadIdx.x;                 // 1024 threads
    out[(size_t)SEQ * NCH + i] = __uint_as_float(g_h[0][i].v);  // S even -> slot 0
}

// ---------------- launch ----------------
extern "C" void kernel_launch(void* const* d_in, const int* in_sizes, int n_in,
                              void* d_out, int out_size)
{
    const int*   input_seq = (const int*)  d_in[0];
    const float* emb       = (const float*)d_in[1];
    const float* Wax       = (const float*)d_in[2];
    const float* Waa       = (const float*)d_in[3];
    const float* Wya       = (const float*)d_in[4];
    const float* b_y       = (const float*)d_in[5];
    float* out = (float*)d_out;

    float* xp_ptr = nullptr;
    float* hs_ptr = nullptr;
    cudaGetSymbolAddress((void**)&xp_ptr, g_xp);
    cudaGetSymbolAddress((void**)&hs_ptr, g_hs);

    // 1) x_proj[s,h] = sum_e emb_table[input_seq[s],e] * Wax[h,e]
    {
        dim3 grid(HID / 128, SEQ / 128);
        sgemm_tn<true, false><<<grid, 256>>>(emb, Wax, xp_ptr, input_seq, nullptr,
                                             SEQ, HID, EMB);
    }
    // 2) reset publish tags, then the sequential scan
    init_tags_kernel<<<1, 256>>>();
    scan_kernel<<<GCTA, 1024>>>(Waa);
    // 3) out[s,v] = sum_h hs[s,h] * Wya[v,h] + b_y[v]
    {
        dim3 grid(NCH / 128, SEQ / 128);
        sgemm_tn<false, true><<<grid, 256>>>(hs_ptr, Wya, out, nullptr, b_y,
                                             SEQ, NCH, HID);
    }
    // 4) append h_last
    copy_hlast_kernel<<<1, HID>>>(out);
}